// round 2
// baseline (speedup 1.0000x reference)
#include <cuda_runtime.h>

#define W 512
#define B 64

// Fused kernel:
//   blocks [0, B*W/4)        -> x-scan, 4 rows per 512-thread CTA
//   blocks [B*W/4, +B*16)    -> y-scan, 32-col x 16-seg per 512-thread CTA
#define X_BLOCKS (B * W / 4)   // 8192
#define Y_BLOCKS (B * 16)      // 1024

__global__ void __launch_bounds__(512) integral_kernel(const float* __restrict__ in,
                                                       float* __restrict__ out) {
    if (blockIdx.x < X_BLOCKS) {
        // ----------------- x-scan: channel 0, contiguous axis -----------------
        // 512 threads = 4 rows x 128 threads. Each thread owns one float4.
        const int t       = threadIdx.x;
        const int rlocal  = t >> 7;          // 0..3  row within CTA
        const int rt      = t & 127;         // 0..127 thread within row
        const int lane    = rt & 31;
        const int rwarp   = rt >> 5;         // 0..3  warp within row

        const int row = blockIdx.x * 4 + rlocal;   // 0 .. B*W-1
        const int b   = row >> 9;
        const int y   = row & (W - 1);
        const size_t base = (size_t)b * 2 * W * W + (size_t)y * W;  // channel 0

        const float4* ip4 = reinterpret_cast<const float4*>(in + base);
        float4 v = __ldcs(ip4 + rt);

        v.y += v.x; v.z += v.y; v.w += v.z;
        float total = v.w;

        #pragma unroll
        for (int d = 1; d < 32; d <<= 1) {
            float n = __shfl_up_sync(0xFFFFFFFFu, total, d);
            if (lane >= d) total += n;
        }

        __shared__ float wsum[4][4];          // [row][warp]
        if (lane == 31) wsum[rlocal][rwarp] = total;
        __syncthreads();

        float woff = 0.0f;
        #pragma unroll
        for (int j = 0; j < 3; j++)
            if (j < rwarp) woff += wsum[rlocal][j];

        const float excl = (total - v.w) + woff;
        v.x += excl; v.y += excl; v.z += excl; v.w += excl;

        __stcs(reinterpret_cast<float4*>(out + base) + rt, v);
    } else {
        // ----------------- y-scan: channel 1, stride-W axis -----------------
        const int blk = blockIdx.x - X_BLOCKS;   // 0 .. B*16-1
        const int b   = blk >> 4;
        const int cg  = blk & 15;
        const int tx  = threadIdx.x & 31;        // column within group
        const int seg = threadIdx.x >> 5;        // 0..15, 32 rows each
        const int col = (cg << 5) + tx;

        const size_t chan_base = ((size_t)b * 2 + 1) * W * W;  // channel 1
        const size_t base = chan_base + (size_t)(seg * 32) * W + col;

        const float* ip = in + base;
        float v[32];

        // batch all strided loads first -> MLP = 32
        #pragma unroll
        for (int i = 0; i < 32; i++)
            v[i] = __ldcs(ip + (size_t)i * W);

        #pragma unroll
        for (int i = 1; i < 32; i++)
            v[i] += v[i - 1];

        __shared__ float s[16][33];              // +1 pad: column-wise reads stay conflict-free
        s[seg][tx] = v[31];
        __syncthreads();

        float off = 0.0f;
        #pragma unroll
        for (int j = 0; j < 15; j++)
            if (j < seg) off += s[j][tx];

        float* op = out + base;
        #pragma unroll
        for (int i = 0; i < 32; i++)
            __stcs(op + (size_t)i * W, v[i] + off);
    }
}

extern "C" void kernel_launch(void* const* d_in, const int* in_sizes, int n_in,
                              void* d_out, int out_size) {
    const float* in = (const float*)d_in[0];
    float* out = (float*)d_out;
    integral_kernel<<<X_BLOCKS + Y_BLOCKS, 512>>>(in, out);
}

// round 4
// speedup vs baseline: 1.3101x; 1.3101x over previous
#include <cuda_runtime.h>

#define W 512
#define B 64

// x-scan: 1 warp per row, 16 rows per 512-thread CTA
#define X_BLOCKS (B * W / 16)          // 2048
// y-scan: CTA covers 16 cols x 512 rows; 32 col-groups per batch
#define Y_BLOCKS (B * (W / 16))        // 2048

__global__ void __launch_bounds__(512, 3)
integral_kernel(const float* __restrict__ in, float* __restrict__ out) {
    const int t = threadIdx.x;

    if (blockIdx.x < X_BLOCKS) {
        // -------- x-scan: channel 0, contiguous axis, warp-per-row --------
        const int warp = t >> 5;
        const int lane = t & 31;
        const int row  = blockIdx.x * 16 + warp;     // 0 .. B*W-1
        const int b    = row >> 9;
        const int y    = row & (W - 1);
        const size_t base = (size_t)b * 2 * W * W + (size_t)y * W;  // channel 0

        const float4* ip4 = reinterpret_cast<const float4*>(in + base) + lane * 4;
        // batch 4 independent float4 loads -> MLP = 4 per thread
        float4 v0 = __ldcs(ip4 + 0);
        float4 v1 = __ldcs(ip4 + 1);
        float4 v2 = __ldcs(ip4 + 2);
        float4 v3 = __ldcs(ip4 + 3);

        // local inclusive scan of 16
        v0.y += v0.x; v0.z += v0.y; v0.w += v0.z;
        v1.x += v0.w; v1.y += v1.x; v1.z += v1.y; v1.w += v1.z;
        v2.x += v1.w; v2.y += v2.x; v2.z += v2.y; v2.w += v2.z;
        v3.x += v2.w; v3.y += v3.x; v3.z += v3.y; v3.w += v3.z;

        const float total = v3.w;
        float scan = total;
        #pragma unroll
        for (int d = 1; d < 32; d <<= 1) {
            float n = __shfl_up_sync(0xFFFFFFFFu, scan, d);
            if (lane >= d) scan += n;
        }
        const float excl = scan - total;   // exclusive prefix from lower lanes

        v0.x += excl; v0.y += excl; v0.z += excl; v0.w += excl;
        v1.x += excl; v1.y += excl; v1.z += excl; v1.w += excl;
        v2.x += excl; v2.y += excl; v2.z += excl; v2.w += excl;
        v3.x += excl; v3.y += excl; v3.z += excl; v3.w += excl;

        float4* op4 = reinterpret_cast<float4*>(out + base) + lane * 4;
        __stcs(op4 + 0, v0);
        __stcs(op4 + 1, v1);
        __stcs(op4 + 2, v2);
        __stcs(op4 + 3, v3);
    } else {
        // -------- y-scan: channel 1, stride-W axis --------
        // block = (16 cols, 32 segments of 16 rows) = 512 threads
        const int blk = blockIdx.x - X_BLOCKS;       // 0 .. B*32-1
        const int b   = blk >> 5;                    // batch
        const int cg  = blk & 31;                    // column group (16 cols each)
        const int tx  = t & 15;
        const int seg = t >> 4;                      // 0..31
        const int col = (cg << 4) + tx;

        const size_t chan_base = ((size_t)b * 2 + 1) * W * W;  // channel 1
        const size_t base = chan_base + (size_t)(seg * 16) * W + col;

        const float* ip = in + base;
        float v[16];
        // batch all 16 strided loads -> MLP = 16 per thread
        #pragma unroll
        for (int i = 0; i < 16; i++)
            v[i] = __ldcs(ip + (size_t)i * W);

        #pragma unroll
        for (int i = 1; i < 16; i++)
            v[i] += v[i - 1];

        __shared__ float s[32][17];   // +1 pad
        s[seg][tx] = v[15];
        __syncthreads();

        float off = 0.0f;
        #pragma unroll
        for (int j = 0; j < 31; j++)
            if (j < seg) off += s[j][tx];

        float* op = out + base;
        #pragma unroll
        for (int i = 0; i < 16; i++)
            __stcs(op + (size_t)i * W, v[i] + off);
    }
}

extern "C" void kernel_launch(void* const* d_in, const int* in_sizes, int n_in,
                              void* d_out, int out_size) {
    const float* in = (const float*)d_in[0];
    float* out = (float*)d_out;
    integral_kernel<<<X_BLOCKS + Y_BLOCKS, 512>>>(in, out);
}